// round 8
// baseline (speedup 1.0000x reference)
#include <cuda_runtime.h>
#include <cuda_bf16.h>
#include <cstdint>

typedef uint32_t u32;

#define CL 8
#define NCTA 128
#define THREADS 512
#define T_LEN 512
#define SA 264                  // A row stride in halves (528 B)
#define MST 132                 // stage row stride in floats

// ---- smem byte offsets ----
#define OFF_AHI 0
#define OFF_ALO 67584           // 128*528
#define OFF_B   135168          // 4 tiles [G][p]{hi 8448 | lo 8448} stride 16896
#define OFF_ST  202752          // 2 groups x 16*132*4 = 8448 each
#define OFF_MBAR 219648
#define SMEM_BYTES 219680

// ---- device scratch ----
__device__ __align__(16) __nv_bfloat16 g_Apack[CL][2][128*SA];
__device__ float g_wih[CL*128];        // [(r*32+hid)*4+g]
__device__ float g_bias[CL*128];
__device__ float g_tsT[T_LEN*512];     // [t][b]
__device__ u32   g_hq[2][512*256];     // [parity][b][k] packed (bf16_lo<<16)|bf16_hi
__device__ float g_part[CL*512];

// ---- asm helpers ----
__device__ __forceinline__ u32 smem_u32(const void* p){
    u32 a;
    asm("{ .reg .u64 t; cvta.to.shared.u64 t, %1; cvt.u32.u64 %0, t; }" : "=r"(a) : "l"(p));
    return a;
}
#define LDSM4(R, addr) \
    asm volatile("ldmatrix.sync.aligned.m8n8.x4.shared.b16 {%0,%1,%2,%3}, [%4];" \
        : "=r"((R)[0]), "=r"((R)[1]), "=r"((R)[2]), "=r"((R)[3]) : "r"(addr))
#define MBAR_INIT(addr, count) \
    asm volatile("mbarrier.init.shared.b64 [%0], %1;" :: "r"(addr), "r"(count) : "memory")
#define MBAR_ARRIVE_CLUSTER(addr, rank) \
    asm volatile("{\n\t.reg .b32 ra;\n\tmapa.shared::cluster.u32 ra, %0, %1;\n\t" \
                 "mbarrier.arrive.shared::cluster.b64 _, [ra];\n\t}" \
                 :: "r"(addr), "r"(rank) : "memory")
#define BAR_SYNC(id)   asm volatile("bar.sync %0, 512;"   :: "r"(id) : "memory")
#define BAR_ARRIVE(id) asm volatile("bar.arrive %0, 512;" :: "r"(id) : "memory")
__device__ __forceinline__ void mbar_wait(u32 mbar, u32 parity){
    asm volatile(
        "{\n\t.reg .pred P;\n\t"
        "W_%=:\n\t"
        "mbarrier.try_wait.parity.acquire.cluster.shared::cta.b64 P, [%0], %1, 0x989680;\n\t"
        "@!P bra W_%=;\n\t}"
        :: "r"(mbar), "r"(parity) : "memory");
}
__device__ __forceinline__ void mma_bf16(float* d, const u32* a, const u32* b){
    asm volatile(
        "mma.sync.aligned.m16n8k16.row.col.f32.bf16.bf16.f32 "
        "{%0,%1,%2,%3}, {%4,%5,%6,%7}, {%8,%9}, {%0,%1,%2,%3};"
        : "+f"(d[0]), "+f"(d[1]), "+f"(d[2]), "+f"(d[3])
        : "r"(a[0]), "r"(a[1]), "r"(a[2]), "r"(a[3]), "r"(b[0]), "r"(b[1]));
}
__device__ __forceinline__ float sigf(float x){
    float e = __expf(-x); return __fdividef(1.f, 1.f + e);
}
__device__ __forceinline__ float tanha(float x){
    float ax = fabsf(x);
    float e = __expf(-2.f*ax);
    float t = __fdividef(1.f - e, 1.f + e);
    return copysignf(t, x);
}

// ---- prep ----
__global__ void prep_kernel(const float* __restrict__ ts, const float* __restrict__ W_ih,
                            const float* __restrict__ W_hh, const float* __restrict__ b_ih,
                            const float* __restrict__ b_hh){
    int i0 = blockIdx.x*blockDim.x + threadIdx.x, stride = gridDim.x*blockDim.x;
    for (int idx = i0; idx < CL*128*256; idx += stride){
        int k = idx & 255, m = (idx>>8)&127, r = idx>>15;
        int hid = m>>2, g = m&3;
        float w = W_hh[(g*256 + r*32 + hid)*256 + k];
        __nv_bfloat16 hi = __float2bfloat16(w);
        __nv_bfloat16 lo = __float2bfloat16(w - __bfloat162float(hi));
        g_Apack[r][0][m*SA + k] = hi;
        g_Apack[r][1][m*SA + k] = lo;
    }
    for (int idx = i0; idx < CL*128; idx += stride){
        int g = idx&3, hid = (idx>>2)&31, r = idx>>7;
        int j = g*256 + r*32 + hid;
        g_wih[idx]  = W_ih[j];
        g_bias[idx] = b_ih[j] + b_hh[j];
    }
    for (int idx = i0; idx < T_LEN*512; idx += stride){
        int b = idx & 511, t = idx >> 9;
        g_tsT[idx] = ts[b*T_LEN + t];
    }
}

__global__ void dummy_kernel(){}

// ---- main: cluster-8 LSTM, warp-specialized GEMM/EXCH pipeline ----
__global__ void __launch_bounds__(THREADS, 1) __cluster_dims__(CL, 1, 1)
lstm_mma(const float* __restrict__ Wout){
    extern __shared__ char smem[];
    u32 sb = smem_u32(smem);
    int tid = threadIdx.x, wid = tid >> 5, lane = tid & 31;
    uint32_t rk; asm("mov.u32 %0, %%cluster_ctarank;" : "=r"(rk));
    int B0 = (blockIdx.x >> 3) * 32;

    // init: A hi+lo -> smem, zero all 4 B tiles (h0 = 0), init mbarriers
    {
        const uint4* src = (const uint4*)&g_Apack[rk][0][0];
        uint4* dst = (uint4*)smem;
        for (int i = tid; i < 135168/16; i += THREADS) dst[i] = src[i];
        uint4* bz = (uint4*)(smem + OFF_B);
        for (int i = tid; i < 67584/16; i += THREADS) bz[i] = make_uint4(0,0,0,0);
    }
    if (tid == 0){ MBAR_INIT(sb + OFF_MBAR, 64); MBAR_INIT(sb + OFF_MBAR + 8, 64); }
    __syncthreads();
    asm volatile("barrier.cluster.arrive.aligned;" ::: "memory");
    asm volatile("barrier.cluster.wait.aligned;"   ::: "memory");

    if (wid < 8){
        // ================= GEMM role (warps 0-7) =================
        int w = wid;
        int q = lane >> 3, r = lane & 7;
        u32 aHiA = sb + (u32)((w*16 + (q&1)*8 + r)*528 + (q>>1)*16);
        u32 aLoA = aHiA + 67584;
        u32 bBase[2][2];
        #pragma unroll
        for (int G = 0; G < 2; ++G)
            #pragma unroll
            for (int p = 0; p < 2; ++p)
                bBase[G][p] = sb + OFF_B + (u32)((G*2+p)*16896)
                            + (u32)((((q>>1)*8 + r)*528) + (q&1)*16);
        int fg = lane >> 2, ft = lane & 3;
        int m0 = w*16 + fg, n0 = ft*2;

        for (int t = 0; t < T_LEN; ++t){
            int p = t & 1;
            #pragma unroll
            for (int G = 0; G < 2; ++G){
                BAR_SYNC(1 + G);                      // B tile ready
                float acc0[4] = {0,0,0,0}, acc1[4] = {0,0,0,0};
                u32 bHiA = bBase[G][p], bLoA = bHiA + 8448;
                #pragma unroll
                for (int kt = 0; kt < 16; ++kt){
                    u32 ah[4], al[4], bh[4], bl[4];
                    LDSM4(ah, aHiA + kt*32);
                    LDSM4(al, aLoA + kt*32);
                    LDSM4(bh, bHiA + kt*32);
                    LDSM4(bl, bLoA + kt*32);
                    mma_bf16(acc0, ah, bh);
                    mma_bf16(acc0, ah, bl);
                    mma_bf16(acc0, al, bh);
                    mma_bf16(acc1, ah, bh + 2);
                    mma_bf16(acc1, ah, bl + 2);
                    mma_bf16(acc1, al, bh + 2);
                }
                float* stG = (float*)(smem + OFF_ST + G*8448);
                stG[n0*MST + m0]           = acc0[0];
                stG[(n0+1)*MST + m0]       = acc0[1];
                stG[n0*MST + m0 + 8]       = acc0[2];
                stG[(n0+1)*MST + m0 + 8]   = acc0[3];
                stG[(n0+8)*MST + m0]       = acc1[0];
                stG[(n0+9)*MST + m0]       = acc1[1];
                stG[(n0+8)*MST + m0 + 8]   = acc1[2];
                stG[(n0+9)*MST + m0 + 8]   = acc1[3];
                BAR_ARRIVE(3 + G);                    // stage ready
            }
        }
    } else {
        // ================= EXCH role (warps 8-15) =================
        int e = tid - 256;
        int hid = e & 31, bb = e >> 5;               // 2 batches: bb*2, bb*2+1
        int ghid = (int)rk*32 + hid;
        float4 wih = ((const float4*)g_wih )[rk*32 + hid];
        float4 bia = ((const float4*)g_bias)[rk*32 + hid];
        float creg[2][2] = {{0,0},{0,0}};
        float oacc[2][2] = {{0,0},{0,0}};
        int rn = e & 15, rks = e >> 4;               // rebuild: row, 16-k slice

        BAR_ARRIVE(1); BAR_ARRIVE(2);                // prime B_ready (tiles zeroed)

        for (int t = 0; t < T_LEN; ++t){
            int wp = t & 1;
            // hoisted LDGs: latency overlaps the stage-ready waits
            float wo = Wout[t*256 + ghid];
            float xv[2][2];
            #pragma unroll
            for (int G = 0; G < 2; ++G)
                #pragma unroll
                for (int j = 0; j < 2; ++j)
                    xv[G][j] = g_tsT[t*512 + B0 + G*16 + bb*2 + j];

            #pragma unroll
            for (int G = 0; G < 2; ++G){
                u32 mbar = sb + OFF_MBAR + G*8;
                BAR_SYNC(3 + G);                      // stage ready
                const float* stG = (const float*)(smem + OFF_ST + G*8448);
                #pragma unroll
                for (int j = 0; j < 2; ++j){
                    int b = bb*2 + j;
                    float4 gq = *(const float4*)(stG + b*MST + hid*4);
                    float x = xv[G][j];
                    float gi = gq.x + fmaf(x, wih.x, bia.x);
                    float gf = gq.y + fmaf(x, wih.y, bia.y);
                    float gg = gq.z + fmaf(x, wih.z, bia.z);
                    float go = gq.w + fmaf(x, wih.w, bia.w);
                    float c  = sigf(gf)*creg[G][j] + sigf(gi)*tanha(gg);
                    creg[G][j] = c;
                    float h  = sigf(go)*tanha(c);
                    oacc[G][j] = fmaf(h, wo, oacc[G][j]);
                    __nv_bfloat16 hb = __float2bfloat16(h);
                    __nv_bfloat16 lb = __float2bfloat16(h - __bfloat162float(hb));
                    g_hq[wp][(size_t)(B0 + G*16 + b)*256 + ghid] =
                        ((u32)__bfloat16_as_ushort(lb) << 16) | (u32)__bfloat16_as_ushort(hb);
                }
                if (t < T_LEN-1){
                    // warp-level release: syncwarp orders all lanes' STGs before
                    // the leader's release-arrives (count 64 = 8 warps x 8 ranks)
                    __syncwarp();
                    if (lane == 0){
                        #pragma unroll
                        for (int dr = 0; dr < CL; ++dr) MBAR_ARRIVE_CLUSTER(mbar, dr);
                    }
                    mbar_wait(mbar, (u32)wp);
                    const uint4* src = (const uint4*)(g_hq[wp] + (size_t)(B0 + G*16 + rn)*256 + rks*16);
                    uint4 q0 = __ldcg(src), q1 = __ldcg(src+1), q2 = __ldcg(src+2), q3 = __ldcg(src+3);
                    uint4 hiA, loA, hiB, loB;
                    hiA.x = __byte_perm(q0.x, q0.y, 0x5410); hiA.y = __byte_perm(q0.z, q0.w, 0x5410);
                    hiA.z = __byte_perm(q1.x, q1.y, 0x5410); hiA.w = __byte_perm(q1.z, q1.w, 0x5410);
                    loA.x = __byte_perm(q0.x, q0.y, 0x7632); loA.y = __byte_perm(q0.z, q0.w, 0x7632);
                    loA.z = __byte_perm(q1.x, q1.y, 0x7632); loA.w = __byte_perm(q1.z, q1.w, 0x7632);
                    hiB.x = __byte_perm(q2.x, q2.y, 0x5410); hiB.y = __byte_perm(q2.z, q2.w, 0x5410);
                    hiB.z = __byte_perm(q3.x, q3.y, 0x5410); hiB.w = __byte_perm(q3.z, q3.w, 0x5410);
                    loB.x = __byte_perm(q2.x, q2.y, 0x7632); loB.y = __byte_perm(q2.z, q2.w, 0x7632);
                    loB.z = __byte_perm(q3.x, q3.y, 0x7632); loB.w = __byte_perm(q3.z, q3.w, 0x7632);
                    char* bt = smem + OFF_B + (G*2 + (wp^1))*16896 + rn*528 + rks*32;
                    *(uint4*)(bt)            = hiA;
                    *(uint4*)(bt + 16)       = hiB;
                    *(uint4*)(bt + 8448)     = loA;
                    *(uint4*)(bt + 8448+16)  = loB;
                    BAR_ARRIVE(1 + G);                // next B tile ready
                }
            }
        }
        // park oacc in stage smem for the epilogue (roles re-converge below)
        {
            float* se = (float*)(smem + OFF_ST);
            se[(0*16 + bb*2 + 0)*33 + hid] = oacc[0][0];
            se[(0*16 + bb*2 + 1)*33 + hid] = oacc[0][1];
            se[(1*16 + bb*2 + 0)*33 + hid] = oacc[1][0];
            se[(1*16 + bb*2 + 1)*33 + hid] = oacc[1][1];
        }
    }

    // ---- epilogue ----
    __syncthreads();
    if (tid < 32){
        const float* se = (const float*)(smem + OFF_ST);
        float s = 0.f;
        for (int h2 = 0; h2 < 32; ++h2) s += se[tid*33 + h2];
        g_part[(size_t)rk*512 + B0 + tid] = s;
    }
    asm volatile("barrier.cluster.arrive.aligned;" ::: "memory");
    asm volatile("barrier.cluster.wait.aligned;"   ::: "memory");
}

// ---- finish ----
__global__ void finish_kernel(const float* __restrict__ b_out, float* __restrict__ out){
    int b = blockIdx.x * blockDim.x + threadIdx.x;
    if (b < 512){
        float s = b_out[0];
        #pragma unroll
        for (int r = 0; r < CL; ++r) s += g_part[r*512 + b];
        out[b] = s;
    }
}

extern "C" void kernel_launch(void* const* d_in, const int* in_sizes, int n_in,
                              void* d_out, int out_size){
    const float* ts    = (const float*)d_in[0];
    const float* W_ih  = (const float*)d_in[1];
    const float* W_hh  = (const float*)d_in[2];
    const float* b_ih  = (const float*)d_in[3];
    const float* b_hh  = (const float*)d_in[4];
    const float* W_out = (const float*)d_in[5];
    const float* b_out = (const float*)d_in[6];
    float* out = (float*)d_out;

    cudaFuncSetAttribute(lstm_mma, cudaFuncAttributeMaxDynamicSharedMemorySize, SMEM_BYTES);
    prep_kernel<<<256, 256>>>(ts, W_ih, W_hh, b_ih, b_hh);
    dummy_kernel<<<1, 32>>>();
    dummy_kernel<<<1, 32>>>();
    lstm_mma<<<NCTA, THREADS, SMEM_BYTES>>>(W_out);   // 16 clusters x 8 CTAs
    finish_kernel<<<2, 256>>>(b_out, out);
}